// round 4
// baseline (speedup 1.0000x reference)
#include <cuda_runtime.h>
#include <cuda_bf16.h>

#define NN 100000
#define NE 3200000
#define CH 128

// Scratch (static device globals: allocation-free per harness rules)
__device__ int   g_is64;                  // 1 if edge_index is int64, 0 if int32
__device__ int   g_cnt[NN];               // in-degree (excl. self loop)
__device__ int   g_off[NN];               // CSR offsets (exclusive scan of cnt)
__device__ int   g_cur[NN];               // scatter cursors
__device__ int   g_csr[NE];               // source ids grouped by target
__device__ float g_dinv[NN];
__device__ float g_xw[(size_t)NN * CH];   // X @ W (unscaled), 51.2 MB (L2-resident)

// ---------------------------------------------------------------------------
// Dtype probe: int64 indices have all-zero high words; int32 pairs do not.
// ---------------------------------------------------------------------------
__global__ void k_detect(const int2* __restrict__ ei) {
    if (threadIdx.x == 0 && blockIdx.x == 0) {
        int any_hi = 0;
#pragma unroll 8
        for (int i = 0; i < 256; i++) any_hi |= ei[i].y;
        g_is64 = (any_hi == 0) ? 1 : 0;
    }
}

__device__ __forceinline__ int edge_at(const void* __restrict__ ei, long long pos) {
    if (g_is64) return (int)((const long long*)ei)[pos];
    return ((const int*)ei)[pos];
}

// ---------------------------------------------------------------------------
// CSR build: count -> scan(+dinv) -> scatter
// ---------------------------------------------------------------------------
__global__ void k_zero_cnt() {
    int i = blockIdx.x * blockDim.x + threadIdx.x;
    if (i < NN) g_cnt[i] = 0;
}

__global__ void k_count(const void* __restrict__ ei) {
    int e = blockIdx.x * blockDim.x + threadIdx.x;
    if (e < NE) atomicAdd(&g_cnt[edge_at(ei, (long long)NE + e)], 1);
}

// Single-block exclusive scan of g_cnt -> g_off/g_cur; also computes g_dinv.
__global__ void __launch_bounds__(1024) k_scan() {
    __shared__ int warp_sums[32];
    const int t    = threadIdx.x;
    const int per  = (NN + 1023) / 1024;              // 98
    const int lane = t & 31, wid = t >> 5;
    int start = t * per;
    int end   = start + per; if (end > NN) end = NN;
    if (start > NN) start = NN;

    int s = 0;
    for (int i = start; i < end; i++) s += g_cnt[i];

    int v = s;
#pragma unroll
    for (int o = 1; o < 32; o <<= 1) {
        int u = __shfl_up_sync(0xFFFFFFFFu, v, o);
        if (lane >= o) v += u;
    }
    if (lane == 31) warp_sums[wid] = v;
    __syncthreads();
    if (wid == 0) {
        int w = warp_sums[lane];
#pragma unroll
        for (int o = 1; o < 32; o <<= 1) {
            int u = __shfl_up_sync(0xFFFFFFFFu, w, o);
            if (lane >= o) w += u;
        }
        warp_sums[lane] = w;
    }
    __syncthreads();

    int run = v - s + (wid > 0 ? warp_sums[wid - 1] : 0);
    for (int i = start; i < end; i++) {
        int c = g_cnt[i];
        g_off[i]  = run;
        g_cur[i]  = run;
        g_dinv[i] = rsqrtf(1.0f + (float)c);
        run += c;
    }
}

__global__ void k_scatter(const void* __restrict__ ei) {
    int e = blockIdx.x * blockDim.x + threadIdx.x;
    if (e < NE) {
        int r = edge_at(ei, e);                     // source
        int c = edge_at(ei, (long long)NE + e);     // target
        int pos = atomicAdd(&g_cur[c], 1);
        g_csr[pos] = r;
    }
}

// ---------------------------------------------------------------------------
// GEMM: g_xw[i][c] = sum_k X[i][k] * W[k][c]   (NO dinv dependency)
// ---------------------------------------------------------------------------
__global__ void __launch_bounds__(256) k_gemm(const float* __restrict__ X,
                                              const float* __restrict__ W) {
    __shared__ float As[16 * 68];   // [k][row], stride 68 (conflict-free, f4-aligned)
    __shared__ float Ws[16 * 128];  // [k][col]

    const int tid = threadIdx.x;
    const int bm  = blockIdx.x * 64;
    const int tx  = tid & 31;
    const int ty  = tid >> 5;
    const int r0  = ty * 8;
    const int c0  = tx * 4;

    float acc[8][4];
#pragma unroll
    for (int j = 0; j < 8; j++)
#pragma unroll
        for (int q = 0; q < 4; q++) acc[j][q] = 0.0f;

    const int arow = tid >> 2;
    const int aq   = tid & 3;

    for (int kk = 0; kk < CH; kk += 16) {
        {
            int grow = bm + arow;
            float4 av = make_float4(0.f, 0.f, 0.f, 0.f);
            if (grow < NN)
                av = *(const float4*)&X[(size_t)grow * CH + kk + aq * 4];
            As[(aq * 4 + 0) * 68 + arow] = av.x;
            As[(aq * 4 + 1) * 68 + arow] = av.y;
            As[(aq * 4 + 2) * 68 + arow] = av.z;
            As[(aq * 4 + 3) * 68 + arow] = av.w;
        }
#pragma unroll
        for (int t = 0; t < 2; t++) {
            int idx = tid + t * 256;
            int wk  = idx >> 5;
            int wc  = (idx & 31) * 4;
            *(float4*)&Ws[wk * 128 + wc] =
                *(const float4*)&W[(size_t)(kk + wk) * CH + wc];
        }
        __syncthreads();

#pragma unroll
        for (int k = 0; k < 16; k++) {
            float4 b  = *(float4*)&Ws[k * 128 + c0];
            float4 a0 = *(float4*)&As[k * 68 + r0];
            float4 a1 = *(float4*)&As[k * 68 + r0 + 4];
            float ar[8] = {a0.x, a0.y, a0.z, a0.w, a1.x, a1.y, a1.z, a1.w};
#pragma unroll
            for (int j = 0; j < 8; j++) {
                acc[j][0] += ar[j] * b.x;
                acc[j][1] += ar[j] * b.y;
                acc[j][2] += ar[j] * b.z;
                acc[j][3] += ar[j] * b.w;
            }
        }
        __syncthreads();
    }

#pragma unroll
    for (int j = 0; j < 8; j++) {
        int grow = bm + r0 + j;
        if (grow < NN)
            *(float4*)&g_xw[(size_t)grow * CH + c0] =
                make_float4(acc[j][0], acc[j][1], acc[j][2], acc[j][3]);
    }
}

// ---------------------------------------------------------------------------
// Pull-mode aggregation: one warp per target node, zero atomics.
//   out[c] = dinv[c] * (dinv[c]*xw[c] + sum_{r} dinv[r]*xw[r]) + bias
// ---------------------------------------------------------------------------
__global__ void __launch_bounds__(256) k_aggr(float* __restrict__ out,
                                              const float* __restrict__ bias) {
    int warp = (blockIdx.x * 256 + threadIdx.x) >> 5;
    int lane = threadIdx.x & 31;
    if (warp >= NN) return;
    const int c   = warp;
    const int off = g_off[c];
    const int n   = g_cnt[c];
    const float sc = g_dinv[c];

    // self-loop term
    float4 vc = *(const float4*)&g_xw[(size_t)c * CH + lane * 4];
    float4 acc = make_float4(sc * vc.x, sc * vc.y, sc * vc.z, sc * vc.w);

    for (int i = 0; i < n; i += 32) {
        int chunk = n - i; if (chunk > 32) chunk = 32;
        int   r  = 0;
        float dr = 0.0f;
        if (lane < chunk) {
            r  = __ldg(&g_csr[off + i + lane]);
            dr = __ldg(&g_dinv[r]);
        }
#pragma unroll 4
        for (int j = 0; j < chunk; j++) {
            int   rj = __shfl_sync(0xFFFFFFFFu, r, j);
            float sj = __shfl_sync(0xFFFFFFFFu, dr, j);
            float4 v = *(const float4*)&g_xw[(size_t)rj * CH + lane * 4];
            acc.x += sj * v.x; acc.y += sj * v.y;
            acc.z += sj * v.z; acc.w += sj * v.w;
        }
    }

    float4 b = *(const float4*)&bias[lane * 4];
    float4 o = make_float4(sc * acc.x + b.x, sc * acc.y + b.y,
                           sc * acc.z + b.z, sc * acc.w + b.w);
    *(float4*)&out[(size_t)c * CH + lane * 4] = o;
}

// ---------------------------------------------------------------------------
extern "C" void kernel_launch(void* const* d_in, const int* in_sizes, int n_in,
                              void* d_out, int out_size) {
    const float* X    = (const float*)d_in[0];
    const void*  ei   = d_in[1];                 // [2, NE], int32 OR int64
    // d_in[2] = batch (unused by GCNConv)
    const float* W    = (const float*)d_in[3];
    const float* bias = (const float*)d_in[4];
    float*       out  = (float*)d_out;

    // One-time host-side stream/event creation (first call is the uncaptured
    // correctness run; subsequent captured replays reuse them).
    static cudaStream_t s_side = nullptr;
    static cudaEvent_t  ev_fork = nullptr, ev_join = nullptr;
    if (s_side == nullptr) {
        cudaStreamCreateWithFlags(&s_side, cudaStreamNonBlocking);
        cudaEventCreateWithFlags(&ev_fork, cudaEventDisableTiming);
        cudaEventCreateWithFlags(&ev_join, cudaEventDisableTiming);
    }

    // ---- fork: GEMM on side stream, CSR build on origin stream ----
    cudaEventRecord(ev_fork, 0);
    cudaStreamWaitEvent(s_side, ev_fork, 0);

    k_gemm<<<(NN + 63) / 64, 256, 0, s_side>>>(X, W);
    cudaEventRecord(ev_join, s_side);

    k_detect<<<1, 32>>>((const int2*)ei);
    k_zero_cnt<<<(NN + 255) / 256, 256>>>();
    k_count<<<(NE + 255) / 256, 256>>>(ei);
    k_scan<<<1, 1024>>>();
    k_scatter<<<(NE + 255) / 256, 256>>>(ei);

    // ---- join, then aggregate ----
    cudaStreamWaitEvent(0, ev_join, 0);
    k_aggr<<<(NN * 32 + 255) / 256, 256>>>(out, bias);
}